// round 7
// baseline (speedup 1.0000x reference)
#include <cuda_runtime.h>
#include <cuda_bf16.h>
#include <cstdint>

// ---------------- problem constants ----------------
#define NBINS       64
#define KDIM        192
#define FC          64
#define TILE_P      128
#define NTHREADS    256
#define MCAP        100000
#define Z_MIN_F     (-3.0f)
#define INV_BIN     16.0f
#define EPS_MEAN    1e-5f
#define EPS_BN      1e-5f

// ---- shared layout (float offsets) ----
// At [128][192]  (A operand, k = 3*bin+comp, XOR-swizzled cols)   24576
// Wt [ 64][192]  (B operand, native layout, same swizzle)         12288
// stg 2 bufs x (z:1152 + r:1152)                                   4608
// npc 128 ints                                                      128
#define SM_AT    0
#define SM_W     24576
#define SM_STG   36864
#define SM_NPC   41472
#define SMEM_FLOATS 41600
#define SMEM_BYTES  (SMEM_FLOATS * 4)   // 166400 -> 1 CTA/SM

// ---------------- global scratch ----------------
__device__ float4 g_X[MCAP * (FC / 4)];
__device__ float  g_sum[FC];
__device__ float  g_sqs[FC];
__device__ float  g_scale[FC];
__device__ float  g_shift[FC];

__device__ __forceinline__ float round_tf32(float x) {
    uint32_t u;
    asm("cvt.rna.tf32.f32 %0, %1;" : "=r"(u) : "f"(x));
    return __uint_as_float(u);
}

// m16n8k8 tf32 mma, D += A*B (accumulate in place)
__device__ __forceinline__ void mma8(float* d, uint32_t a0, uint32_t a1,
                                     uint32_t a2, uint32_t a3,
                                     uint32_t b0, uint32_t b1) {
    asm volatile(
        "mma.sync.aligned.m16n8k8.row.col.f32.tf32.tf32.f32 "
        "{%0,%1,%2,%3}, {%4,%5,%6,%7}, {%8,%9}, {%0,%1,%2,%3};"
        : "+f"(d[0]), "+f"(d[1]), "+f"(d[2]), "+f"(d[3])
        : "r"(a0), "r"(a1), "r"(a2), "r"(a3), "r"(b0), "r"(b1));
}

// ---------------- kernel 1: persistent hist + tf32 mma.sync GEMM ----------------
__global__ void __launch_bounds__(NTHREADS, 1)
main_kernel(const float* __restrict__ feat,
            const int*   __restrict__ nump,
            const float* __restrict__ W,
            const float* __restrict__ bbias,
            int M, int ntiles)
{
    extern __shared__ float sm[];
    float* At  = sm + SM_AT;
    float* Wt  = sm + SM_W;
    float* stg = sm + SM_STG;
    int*   npc = (int*)(sm + SM_NPC);

    const int tid = threadIdx.x;

    // ---- one-time: stage W (tf32-rounded, swizzled cols) ----
    {
        const float4* W4 = (const float4*)W;
        for (int i = tid; i < (FC * KDIM) / 4; i += NTHREADS) {
            float4 v = W4[i];
            int c  = i / 48;
            int k4 = (i - c * 48) * 4;
            v.x = round_tf32(v.x); v.y = round_tf32(v.y);
            v.z = round_tf32(v.z); v.w = round_tf32(v.w);
            int colp = k4 ^ ((c & 7) << 2);       // swz bits 2-4; k4 mult of 4 -> float4 intact
            *(float4*)(Wt + c * 192 + colp) = v;
        }
    }

    // GEMM thread geometry (fixed per thread)
    const int lane = tid & 31;
    const int wpi  = tid >> 5;      // warp 0..7 -> pillar group
    const int gid  = lane >> 2;     // 0..7
    const int tig  = lane & 3;      // 0..3
    const int gswz = gid << 2;
    const int p0   = wpi * 16;

    // bias fragments: d cols = 8j + 2*tig (+1)
    float2 bias2[8];
    #pragma unroll
    for (int j = 0; j < 8; j++)
        bias2[j] = *(const float2*)(bbias + j * 8 + 2 * tig);

    // staging geometry
    const int sp = tid >> 3;        // 0..31 (+32u)
    const int sj = tid & 7;

    // hist geometry
    const int hswz = (tid & 7) << 2;           // row = tid (<128)
    float* hrow = At + tid * 192;

    for (int tile = blockIdx.x; tile < ntiles; tile += gridDim.x) {
        const int base = tile * TILE_P;
        __syncthreads();            // protect At reuse across tiles

        // ---- zero At + npc ----
        {
            float4 z4 = make_float4(0.f, 0.f, 0.f, 0.f);
            float4* A4 = (float4*)At;
            #pragma unroll
            for (int i = tid; i < (TILE_P * KDIM) / 4; i += NTHREADS) A4[i] = z4;
        }
        if (tid < TILE_P) {
            int gp = base + tid;
            npc[tid] = (gp < M) ? nump[gp] : 0;
        }
        // prefetch chunk 0
        float2 pf[4];
        #pragma unroll
        for (int u = 0; u < 4; u++) {
            int p = sp + u * 32;
            int gp = base + p;
            pf[u] = make_float2(0.f, 0.f);
            if (gp < M) pf[u] = *(const float2*)(feat + (size_t)gp * 256 + sj * 4 + 2);
        }
        __syncthreads();
        #pragma unroll
        for (int u = 0; u < 4; u++) {
            int p = sp + u * 32;
            stg[p * 9 + sj]        = pf[u].x;
            stg[1152 + p * 9 + sj] = pf[u].y;
        }
        __syncthreads();

        // ---- histogram: 8 chunks, double-buffered ----
        const int np = (tid < TILE_P) ? npc[tid] : 0;
        for (int ch = 0; ch < 8; ch++) {
            int cur = ch & 1;
            if (ch < 7) {
                #pragma unroll
                for (int u = 0; u < 4; u++) {
                    int p = sp + u * 32;
                    int gp = base + p;
                    pf[u] = make_float2(0.f, 0.f);
                    if (gp < M)
                        pf[u] = *(const float2*)(feat + (size_t)gp * 256 + ((ch + 1) * 8 + sj) * 4 + 2);
                }
            }
            if (tid < TILE_P) {
                const float* zb = stg + cur * 2304 + tid * 9;
                const float* rb = zb + 1152;
                #pragma unroll
                for (int j = 0; j < 8; j++) {
                    if (ch * 8 + j < np) {
                        float z = zb[j], r = rb[j];
                        int bin = (int)((z - Z_MIN_F) * INV_BIN);
                        bin = max(0, min(NBINS - 1, bin));
                        int k3 = 3 * bin;
                        float* pc = hrow + ((k3)     ^ hswz);
                        float* pz = hrow + ((k3 + 1) ^ hswz);
                        float* pr = hrow + ((k3 + 2) ^ hswz);
                        float c0 = *pc;
                        float s0 = *pz;
                        float r0 = *pr;
                        *pc = c0 + 1.0f;
                        *pz = s0 + z;
                        *pr = r0 + r;
                    }
                }
            }
            if (ch < 7) {
                int nb = (cur ^ 1) * 2304;
                #pragma unroll
                for (int u = 0; u < 4; u++) {
                    int p = sp + u * 32;
                    stg[nb + p * 9 + sj]        = pf[u].x;
                    stg[nb + 1152 + p * 9 + sj] = pf[u].y;
                }
            }
            __syncthreads();
        }

        // ---- sums -> means, tf32-rounded (lanes span bins: conflict-free) ----
        #pragma unroll
        for (int idx = tid; idx < TILE_P * NBINS; idx += NTHREADS) {
            int bin = idx & 63;
            int p   = idx >> 6;
            int swz = (p & 7) << 2;
            float* row = At + p * 192;
            int k3 = 3 * bin;
            float* pc = row + ((k3)     ^ swz);
            float* pz = row + ((k3 + 1) ^ swz);
            float* pr = row + ((k3 + 2) ^ swz);
            float inv = __frcp_rn(*pc + EPS_MEAN);
            *pz = round_tf32(*pz * inv);
            *pr = round_tf32(*pr * inv);
        }
        __syncthreads();

        // ---- GEMM: D[128p][64c] = At[128][192] x Wt[64][192]^T via m16n8k8 tf32 ----
        float d[8][4];
        #pragma unroll
        for (int j = 0; j < 8; j++) {
            d[j][0] = bias2[j].x; d[j][1] = bias2[j].y;
            d[j][2] = bias2[j].x; d[j][3] = bias2[j].y;
        }
        {
            const float* Ar0 = At + (p0 + gid) * 192;
            const float* Ar1 = Ar0 + 8 * 192;
            const float* Wg  = Wt + gid * 192;
            #pragma unroll 4
            for (int s = 0; s < 24; s++) {
                int col  = ((s << 3) | tig) ^ gswz;
                int colx = col ^ 4;
                uint32_t a0 = __float_as_uint(Ar0[col]);
                uint32_t a1 = __float_as_uint(Ar1[col]);
                uint32_t a2 = __float_as_uint(Ar0[colx]);
                uint32_t a3 = __float_as_uint(Ar1[colx]);
                #pragma unroll
                for (int j = 0; j < 8; j++) {
                    const float* wr = Wg + j * (8 * 192);
                    uint32_t b0 = __float_as_uint(wr[col]);
                    uint32_t b1 = __float_as_uint(wr[colx]);
                    mma8(d[j], a0, a1, a2, a3, b0, b1);
                }
            }
        }

        // ---- epilogue: store x rows (float2, 32B/row clusters) ----
        {
            int gp0 = base + p0 + gid;
            int gp1 = gp0 + 8;
            float2* gx = (float2*)g_X;
            if (gp0 < M) {
                #pragma unroll
                for (int j = 0; j < 8; j++)
                    gx[gp0 * 32 + j * 4 + tig] = make_float2(d[j][0], d[j][1]);
            }
            if (gp1 < M) {
                #pragma unroll
                for (int j = 0; j < 8; j++)
                    gx[gp1 * 32 + j * 4 + tig] = make_float2(d[j][2], d[j][3]);
            }
        }
    }
}

// ---------------- kernel 2: BN sum/sumsq reduction over g_X ----------------
__global__ void __launch_bounds__(256)
reduce_kernel(int M)
{
    __shared__ float4 ss[256], qq[256];
    int gtid  = blockIdx.x * 256 + threadIdx.x;
    int quad  = gtid & 15;
    int row0  = gtid >> 4;
    int rstep = (gridDim.x * 256) >> 4;

    float4 s = make_float4(0.f, 0.f, 0.f, 0.f);
    float4 q = make_float4(0.f, 0.f, 0.f, 0.f);
    for (int r = row0; r < M; r += rstep) {
        float4 v = g_X[r * 16 + quad];
        s.x += v.x; s.y += v.y; s.z += v.z; s.w += v.w;
        q.x += v.x * v.x; q.y += v.y * v.y; q.z += v.z * v.z; q.w += v.w * v.w;
    }
    int t = threadIdx.x;
    ss[(t & 15) * 16 + (t >> 4)] = s;
    qq[(t & 15) * 16 + (t >> 4)] = q;
    __syncthreads();
    if (t < 16) {
        float4 ts = make_float4(0.f, 0.f, 0.f, 0.f);
        float4 tq = make_float4(0.f, 0.f, 0.f, 0.f);
        #pragma unroll
        for (int g = 0; g < 16; g++) {
            float4 a = ss[t * 16 + g];
            float4 b = qq[t * 16 + g];
            ts.x += a.x; ts.y += a.y; ts.z += a.z; ts.w += a.w;
            tq.x += b.x; tq.y += b.y; tq.z += b.z; tq.w += b.w;
        }
        atomicAdd(&g_sum[t * 4 + 0], ts.x);
        atomicAdd(&g_sum[t * 4 + 1], ts.y);
        atomicAdd(&g_sum[t * 4 + 2], ts.z);
        atomicAdd(&g_sum[t * 4 + 3], ts.w);
        atomicAdd(&g_sqs[t * 4 + 0], tq.x);
        atomicAdd(&g_sqs[t * 4 + 1], tq.y);
        atomicAdd(&g_sqs[t * 4 + 2], tq.z);
        atomicAdd(&g_sqs[t * 4 + 3], tq.w);
    }
}

// ---------------- kernel 3: finalize BN scale/shift ----------------
__global__ void finalize_kernel(const float* __restrict__ gamma,
                                const float* __restrict__ beta,
                                int M)
{
    int c = threadIdx.x;
    if (c < FC) {
        float invM = 1.0f / (float)M;
        float mu   = g_sum[c] * invM;
        float var  = g_sqs[c] * invM - mu * mu;
        var = fmaxf(var, 0.0f);
        float sc = gamma[c] * rsqrtf(var + EPS_BN);
        g_scale[c] = sc;
        g_shift[c] = beta[c] - mu * sc;
    }
}

// ---------------- kernel 4: normalize + ReLU + reset accumulators ----------------
__global__ void __launch_bounds__(256)
apply_kernel(float4* __restrict__ out, int M)
{
    int n4 = M * (FC / 4);
    int gid = blockIdx.x * blockDim.x + threadIdx.x;
    int stride = gridDim.x * blockDim.x;

    float4 x[4];
    int idx[4];
    #pragma unroll
    for (int u = 0; u < 4; u++) {
        int i = gid + u * stride;
        idx[u] = i;
        if (i < n4) x[u] = g_X[i];
    }
    #pragma unroll
    for (int u = 0; u < 4; u++) {
        int i = idx[u];
        if (i < n4) {
            int cb = (i & 15) * 4;
            float4 sc = *(const float4*)&g_scale[cb];
            float4 sh = *(const float4*)&g_shift[cb];
            float4 r;
            r.x = fmaxf(fmaf(x[u].x, sc.x, sh.x), 0.0f);
            r.y = fmaxf(fmaf(x[u].y, sc.y, sh.y), 0.0f);
            r.z = fmaxf(fmaf(x[u].z, sc.z, sh.z), 0.0f);
            r.w = fmaxf(fmaf(x[u].w, sc.w, sh.w), 0.0f);
            out[i] = r;
        }
    }
    if (blockIdx.x == 0 && threadIdx.x < FC) {
        g_sum[threadIdx.x] = 0.0f;
        g_sqs[threadIdx.x] = 0.0f;
    }
}

// ---------------- launch ----------------
extern "C" void kernel_launch(void* const* d_in, const int* in_sizes, int n_in,
                              void* d_out, int out_size)
{
    const float* feat  = (const float*)d_in[0];
    const int*   nump  = (const int*)  d_in[1];
    const float* W     = (const float*)d_in[3];
    const float* bbias = (const float*)d_in[4];
    const float* gamma = (const float*)d_in[5];
    const float* beta  = (const float*)d_in[6];
    float4* out = (float4*)d_out;

    int M = in_sizes[1];
    if (M > MCAP) M = MCAP;
    int ntiles = (M + TILE_P - 1) / TILE_P;

    cudaFuncSetAttribute(main_kernel, cudaFuncAttributeMaxDynamicSharedMemorySize, SMEM_BYTES);

    int grid = ntiles < 148 ? ntiles : 148;
    main_kernel<<<grid, NTHREADS, SMEM_BYTES>>>(feat, nump, W, bbias, M, ntiles);
    reduce_kernel<<<148, 256>>>(M);
    finalize_kernel<<<1, 64>>>(gamma, beta, M);
    int n4 = M * (FC / 4);
    int blocks = ((n4 + 3) / 4 + 255) / 256;
    apply_kernel<<<blocks, 256>>>(out, M);
}

// round 8
// speedup vs baseline: 1.2190x; 1.2190x over previous
#include <cuda_runtime.h>
#include <cuda_bf16.h>
#include <cstdint>

// ---------------- problem constants ----------------
#define NBINS       64
#define KDIM        192
#define FC          64
#define TILE_P      128
#define NTHREADS    256
#define MCAP        100000
#define Z_MIN_F     (-3.0f)
#define INV_BIN     16.0f
#define EPS_MEAN    1e-5f
#define EPS_BN      1e-5f

// ---- shared layout (float offsets) ----
// At  [128][192]  swizzled mma A operand      24576  (96KB)
// Wt  [ 64][192]  swizzled mma B operand      12288  (48KB)
// stg 4 ring bufs x [128 pillars x 9 float4]  18432  (72KB)
#define SM_AT    0
#define SM_W     24576
#define SM_STG   36864
#define STG_BUF  4608          // floats per ring buffer
#define SMEM_FLOATS (SM_STG + 4 * STG_BUF)
#define SMEM_BYTES  (SMEM_FLOATS * 4)   // 221184 -> 1 CTA/SM

// ---------------- global scratch ----------------
__device__ float4 g_X[MCAP * (FC / 4)];
__device__ float  g_sum[FC];
__device__ float  g_sqs[FC];
__device__ float  g_scale[FC];
__device__ float  g_shift[FC];

__device__ __forceinline__ float round_tf32(float x) {
    uint32_t u;
    asm("cvt.rna.tf32.f32 %0, %1;" : "=r"(u) : "f"(x));
    return __uint_as_float(u);
}
__device__ __forceinline__ uint32_t smem_u32(const void* p) {
    uint32_t a;
    asm("{ .reg .u64 t; cvta.to.shared.u64 t, %1; cvt.u32.u64 %0, t; }" : "=r"(a) : "l"(p));
    return a;
}
__device__ __forceinline__ void cp16(uint32_t saddr, const void* g) {
    asm volatile("cp.async.cg.shared.global [%0], [%1], 16;" :: "r"(saddr), "l"(g) : "memory");
}
__device__ __forceinline__ void cp_commit() {
    asm volatile("cp.async.commit_group;" ::: "memory");
}
__device__ __forceinline__ void cp_wait(int n) {
    if (n == 0)      asm volatile("cp.async.wait_group 0;" ::: "memory");
    else if (n == 1) asm volatile("cp.async.wait_group 1;" ::: "memory");
    else             asm volatile("cp.async.wait_group 2;" ::: "memory");
}

// m16n8k8 tf32 mma, D += A*B
__device__ __forceinline__ void mma8(float* d, uint32_t a0, uint32_t a1,
                                     uint32_t a2, uint32_t a3,
                                     uint32_t b0, uint32_t b1) {
    asm volatile(
        "mma.sync.aligned.m16n8k8.row.col.f32.tf32.tf32.f32 "
        "{%0,%1,%2,%3}, {%4,%5,%6,%7}, {%8,%9}, {%0,%1,%2,%3};"
        : "+f"(d[0]), "+f"(d[1]), "+f"(d[2]), "+f"(d[3])
        : "r"(a0), "r"(a1), "r"(a2), "r"(a3), "r"(b0), "r"(b1));
}

// ---------------- kernel 1: persistent hist + tf32 mma GEMM + fused BN stats ----------------
__global__ void __launch_bounds__(NTHREADS)
main_kernel(const float* __restrict__ feat,
            const int*   __restrict__ nump,
            const float* __restrict__ W,
            const float* __restrict__ bbias,
            int M, int ntiles)
{
    extern __shared__ float sm[];
    float* At   = sm + SM_AT;
    float* Wt   = sm + SM_W;
    float* stgf = sm + SM_STG;
    const uint32_t stg_b = smem_u32(sm) + SM_STG * 4;   // byte address of stage base

    const int tid = threadIdx.x;

    // ---- one-time: stage W (tf32-rounded, swizzled cols) ----
    {
        const float4* W4 = (const float4*)W;
        for (int i = tid; i < (FC * KDIM) / 4; i += NTHREADS) {
            float4 v = W4[i];
            int c  = i / 48;
            int k4 = (i - c * 48) * 4;
            v.x = round_tf32(v.x); v.y = round_tf32(v.y);
            v.z = round_tf32(v.z); v.w = round_tf32(v.w);
            int colp = k4 ^ ((c & 7) << 2);
            *(float4*)(Wt + c * 192 + colp) = v;
        }
    }

    // GEMM thread geometry
    const int lane = tid & 31;
    const int wpi  = tid >> 5;
    const int gid  = lane >> 2;
    const int tig  = lane & 3;
    const int gswz = gid << 2;
    const int p0   = wpi * 16;

    float2 bias2[8];
    #pragma unroll
    for (int j = 0; j < 8; j++)
        bias2[j] = *(const float2*)(bbias + j * 8 + 2 * tig);

    // BN register accumulators (channel set fixed per thread)
    float2 s2[8], q2[8];
    #pragma unroll
    for (int j = 0; j < 8; j++) {
        s2[j] = make_float2(0.f, 0.f);
        q2[j] = make_float2(0.f, 0.f);
    }

    // staging geometry: element e = tid + u*256 -> pillar (tid>>3)+u*32, point tid&7
    const int spb = tid >> 3;
    const int pt  = tid & 7;

    // hist geometry
    const int hswz = (tid & 7) << 2;
    float* hrow = At + tid * 192;

    for (int tile = blockIdx.x; tile < ntiles; tile += gridDim.x) {
        const int base = tile * TILE_P;
        __syncthreads();   // At / stage ring safe to reuse

        // per-tile num_points (staging pillars + hist pillar)
        int np4[4];
        #pragma unroll
        for (int u = 0; u < 4; u++) {
            int gp = base + spb + u * 32;
            np4[u] = (gp < M) ? nump[gp] : 0;
        }
        const int npt = (tid < TILE_P && base + tid < M) ? nump[base + tid] : 0;

        // issue chunks 0..2 (predicated on live points)
        #pragma unroll
        for (int c0 = 0; c0 < 3; c0++) {
            #pragma unroll
            for (int u = 0; u < 4; u++) {
                int p = spb + u * 32;
                if (np4[u] > c0 * 8) {
                    uint32_t dst = stg_b + c0 * (STG_BUF * 4) + (p * 9 + pt) * 16;
                    cp16(dst, feat + (size_t)(base + p) * 256 + c0 * 32 + pt * 4);
                }
            }
            cp_commit();
        }

        // zero At while loads fly
        {
            float4 z4 = make_float4(0.f, 0.f, 0.f, 0.f);
            float4* A4 = (float4*)At;
            #pragma unroll
            for (int i = tid; i < (TILE_P * KDIM) / 4; i += NTHREADS) A4[i] = z4;
        }

        // ---- pipelined histogram over 8 chunks ----
        #pragma unroll
        for (int ch = 0; ch < 8; ch++) {
            cp_wait(ch <= 5 ? 2 : 7 - ch);
            __syncthreads();
            if (ch < 5) {
                int cn = ch + 3;
                #pragma unroll
                for (int u = 0; u < 4; u++) {
                    int p = spb + u * 32;
                    if (np4[u] > cn * 8) {
                        uint32_t dst = stg_b + (cn & 3) * (STG_BUF * 4) + (p * 9 + pt) * 16;
                        cp16(dst, feat + (size_t)(base + p) * 256 + cn * 32 + pt * 4);
                    }
                }
                cp_commit();
            }
            if (tid < TILE_P) {
                const float* buf = stgf + (ch & 3) * STG_BUF;
                #pragma unroll
                for (int j = 0; j < 8; j++) {
                    if (ch * 8 + j < npt) {
                        float4 v = *(const float4*)(buf + (tid * 9 + j) * 4);
                        float z = v.z, r = v.w;
                        int bin = (int)((z - Z_MIN_F) * INV_BIN);
                        bin = max(0, min(NBINS - 1, bin));
                        int k3 = 3 * bin;
                        float* pc = hrow + ((k3)     ^ hswz);
                        float* pz = hrow + ((k3 + 1) ^ hswz);
                        float* pr = hrow + ((k3 + 2) ^ hswz);
                        float c0 = *pc;
                        float s0 = *pz;
                        float r0 = *pr;
                        *pc = c0 + 1.0f;
                        *pz = s0 + z;
                        *pr = r0 + r;
                    }
                }
            }
        }
        __syncthreads();

        // ---- sums -> means, tf32-rounded ----
        #pragma unroll
        for (int idx = tid; idx < TILE_P * NBINS; idx += NTHREADS) {
            int bin = idx & 63;
            int p   = idx >> 6;
            int swz = (p & 7) << 2;
            float* row = At + p * 192;
            int k3 = 3 * bin;
            float* pc = row + ((k3)     ^ swz);
            float* pz = row + ((k3 + 1) ^ swz);
            float* pr = row + ((k3 + 2) ^ swz);
            float inv = __frcp_rn(*pc + EPS_MEAN);
            *pz = round_tf32(*pz * inv);
            *pr = round_tf32(*pr * inv);
        }
        __syncthreads();

        // ---- GEMM: D[128p][64c] via m16n8k8 tf32 ----
        float d[8][4];
        #pragma unroll
        for (int j = 0; j < 8; j++) {
            d[j][0] = bias2[j].x; d[j][1] = bias2[j].y;
            d[j][2] = bias2[j].x; d[j][3] = bias2[j].y;
        }
        {
            const float* Ar0 = At + (p0 + gid) * 192;
            const float* Ar1 = Ar0 + 8 * 192;
            const float* Wg  = Wt + gid * 192;
            #pragma unroll 4
            for (int s = 0; s < 24; s++) {
                int col  = ((s << 3) | tig) ^ gswz;
                int colx = col ^ 4;
                uint32_t a0 = __float_as_uint(Ar0[col]);
                uint32_t a1 = __float_as_uint(Ar1[col]);
                uint32_t a2 = __float_as_uint(Ar0[colx]);
                uint32_t a3 = __float_as_uint(Ar1[colx]);
                #pragma unroll
                for (int j = 0; j < 8; j++) {
                    const float* wr = Wg + j * (8 * 192);
                    uint32_t b0 = __float_as_uint(wr[col]);
                    uint32_t b1 = __float_as_uint(wr[colx]);
                    mma8(d[j], a0, a1, a2, a3, b0, b1);
                }
            }
        }

        // ---- epilogue: store x, accumulate BN partials in registers ----
        {
            int gp0 = base + p0 + gid;
            int gp1 = gp0 + 8;
            float2* gx = (float2*)g_X;
            if (gp0 < M) {
                #pragma unroll
                for (int j = 0; j < 8; j++) {
                    gx[gp0 * 32 + j * 4 + tig] = make_float2(d[j][0], d[j][1]);
                    s2[j].x += d[j][0]; s2[j].y += d[j][1];
                    q2[j].x += d[j][0] * d[j][0];
                    q2[j].y += d[j][1] * d[j][1];
                }
            }
            if (gp1 < M) {
                #pragma unroll
                for (int j = 0; j < 8; j++) {
                    gx[gp1 * 32 + j * 4 + tig] = make_float2(d[j][2], d[j][3]);
                    s2[j].x += d[j][2]; s2[j].y += d[j][3];
                    q2[j].x += d[j][2] * d[j][2];
                    q2[j].y += d[j][3] * d[j][3];
                }
            }
        }
    }

    // ---- final BN reduction: regs -> smem -> global atomics ----
    __syncthreads();
    float2* Ssm = (float2*)sm;          // At region dead
    float2* Qsm = Ssm + 2048;
    #pragma unroll
    for (int j = 0; j < 8; j++) {
        Ssm[tid * 8 + j] = s2[j];
        Qsm[tid * 8 + j] = q2[j];
    }
    __syncthreads();
    if (tid < FC) {
        int j  = tid >> 3;
        int tg = (tid & 7) >> 1;
        int e  = tid & 1;
        float ts = 0.f, tq = 0.f;
        #pragma unroll
        for (int w = 0; w < 8; w++) {
            #pragma unroll
            for (int g = 0; g < 8; g++) {
                int src = (w * 32 + g * 4 + tg) * 8 + j;
                float2 vs = Ssm[src];
                float2 vq = Qsm[src];
                ts += e ? vs.y : vs.x;
                tq += e ? vq.y : vq.x;
            }
        }
        atomicAdd(&g_sum[tid], ts);
        atomicAdd(&g_sqs[tid], tq);
    }
}

// ---------------- kernel 2: finalize BN scale/shift ----------------
__global__ void finalize_kernel(const float* __restrict__ gamma,
                                const float* __restrict__ beta,
                                int M)
{
    int c = threadIdx.x;
    if (c < FC) {
        float invM = 1.0f / (float)M;
        float mu   = g_sum[c] * invM;
        float var  = g_sqs[c] * invM - mu * mu;
        var = fmaxf(var, 0.0f);
        float sc = gamma[c] * rsqrtf(var + EPS_BN);
        g_scale[c] = sc;
        g_shift[c] = beta[c] - mu * sc;
    }
}

// ---------------- kernel 3: normalize + ReLU + reset accumulators ----------------
__global__ void __launch_bounds__(256)
apply_kernel(float4* __restrict__ out, int M)
{
    int n4 = M * (FC / 4);
    int gid = blockIdx.x * blockDim.x + threadIdx.x;
    int stride = gridDim.x * blockDim.x;

    float4 x[4];
    int idx[4];
    #pragma unroll
    for (int u = 0; u < 4; u++) {
        int i = gid + u * stride;
        idx[u] = i;
        if (i < n4) x[u] = g_X[i];
    }
    #pragma unroll
    for (int u = 0; u < 4; u++) {
        int i = idx[u];
        if (i < n4) {
            int cb = (i & 15) * 4;
            float4 sc = *(const float4*)&g_scale[cb];
            float4 sh = *(const float4*)&g_shift[cb];
            float4 r;
            r.x = fmaxf(fmaf(x[u].x, sc.x, sh.x), 0.0f);
            r.y = fmaxf(fmaf(x[u].y, sc.y, sh.y), 0.0f);
            r.z = fmaxf(fmaf(x[u].z, sc.z, sh.z), 0.0f);
            r.w = fmaxf(fmaf(x[u].w, sc.w, sh.w), 0.0f);
            out[i] = r;
        }
    }
    if (blockIdx.x == 0 && threadIdx.x < FC) {
        g_sum[threadIdx.x] = 0.0f;
        g_sqs[threadIdx.x] = 0.0f;
    }
}

// ---------------- launch ----------------
extern "C" void kernel_launch(void* const* d_in, const int* in_sizes, int n_in,
                              void* d_out, int out_size)
{
    const float* feat  = (const float*)d_in[0];
    const int*   nump  = (const int*)  d_in[1];
    const float* W     = (const float*)d_in[3];
    const float* bbias = (const float*)d_in[4];
    const float* gamma = (const float*)d_in[5];
    const float* beta  = (const float*)d_in[6];
    float4* out = (float4*)d_out;

    int M = in_sizes[1];
    if (M > MCAP) M = MCAP;
    int ntiles = (M + TILE_P - 1) / TILE_P;

    cudaFuncSetAttribute(main_kernel, cudaFuncAttributeMaxDynamicSharedMemorySize, SMEM_BYTES);

    int grid = ntiles < 148 ? ntiles : 148;
    main_kernel<<<grid, NTHREADS, SMEM_BYTES>>>(feat, nump, W, bbias, M, ntiles);
    finalize_kernel<<<1, 64>>>(gamma, beta, M);
    int n4 = M * (FC / 4);
    int blocks = ((n4 + 3) / 4 + 255) / 256;
    apply_kernel<<<blocks, 256>>>(out, M);
}

// round 9
// speedup vs baseline: 1.3804x; 1.1324x over previous
#include <cuda_runtime.h>
#include <cuda_bf16.h>
#include <cstdint>

// ---------------- problem constants ----------------
#define NBINS       64
#define KDIM        192
#define FC          64
#define TILE_P      128
#define NTHREADS    512
#define MCAP        100000
#define Z_MIN_F     (-3.0f)
#define INV_BIN     16.0f
#define EPS_MEAN    1e-5f
#define EPS_BN      1e-5f

// ---- shared layout (float offsets) ----
#define SM_AT    0
#define SM_W     24576
#define SM_STG   36864
#define STG_BUF  4608
#define SMEM_FLOATS (SM_STG + 4 * STG_BUF)
#define SMEM_BYTES  (SMEM_FLOATS * 4)   // 221184 -> 1 CTA/SM

// ---------------- global scratch ----------------
__device__ float4 g_X[MCAP * (FC / 4)];
__device__ float  g_sum[FC];
__device__ float  g_sqs[FC];
__device__ float  g_scale[FC];
__device__ float  g_shift[FC];

__device__ __forceinline__ float round_tf32(float x) {
    uint32_t u;
    asm("cvt.rna.tf32.f32 %0, %1;" : "=r"(u) : "f"(x));
    return __uint_as_float(u);
}
__device__ __forceinline__ uint32_t smem_u32(const void* p) {
    uint32_t a;
    asm("{ .reg .u64 t; cvta.to.shared.u64 t, %1; cvt.u32.u64 %0, t; }" : "=r"(a) : "l"(p));
    return a;
}
__device__ __forceinline__ void cp16(uint32_t saddr, const void* g) {
    asm volatile("cp.async.cg.shared.global [%0], [%1], 16;" :: "r"(saddr), "l"(g) : "memory");
}
__device__ __forceinline__ void cp_commit() {
    asm volatile("cp.async.commit_group;" ::: "memory");
}
__device__ __forceinline__ void cp_wait(int n) {
    if (n == 0)      asm volatile("cp.async.wait_group 0;" ::: "memory");
    else if (n == 1) asm volatile("cp.async.wait_group 1;" ::: "memory");
    else             asm volatile("cp.async.wait_group 2;" ::: "memory");
}

__device__ __forceinline__ void mma8(float* d, uint32_t a0, uint32_t a1,
                                     uint32_t a2, uint32_t a3,
                                     uint32_t b0, uint32_t b1) {
    asm volatile(
        "mma.sync.aligned.m16n8k8.row.col.f32.tf32.tf32.f32 "
        "{%0,%1,%2,%3}, {%4,%5,%6,%7}, {%8,%9}, {%0,%1,%2,%3};"
        : "+f"(d[0]), "+f"(d[1]), "+f"(d[2]), "+f"(d[3])
        : "r"(a0), "r"(a1), "r"(a2), "r"(a3), "r"(b0), "r"(b1));
}

// ---------------- kernel 1: persistent hist + tf32 mma GEMM + fused BN ----------------
__global__ void __launch_bounds__(NTHREADS)
main_kernel(const float* __restrict__ feat,
            const int*   __restrict__ nump,
            const float* __restrict__ W,
            const float* __restrict__ bbias,
            int M, int ntiles)
{
    extern __shared__ float sm[];
    float* At   = sm + SM_AT;
    float* Wt   = sm + SM_W;
    float* stgf = sm + SM_STG;
    const uint32_t stg_b = smem_u32(sm) + SM_STG * 4;

    const int tid = threadIdx.x;

    // ---- one-time: stage W (tf32-rounded, swizzled cols) ----
    {
        const float4* W4 = (const float4*)W;
        for (int i = tid; i < (FC * KDIM) / 4; i += NTHREADS) {
            float4 v = W4[i];
            int c  = i / 48;
            int k4 = (i - c * 48) * 4;
            v.x = round_tf32(v.x); v.y = round_tf32(v.y);
            v.z = round_tf32(v.z); v.w = round_tf32(v.w);
            int colp = k4 ^ ((c & 7) << 2);
            *(float4*)(Wt + c * 192 + colp) = v;
        }
    }

    // GEMM thread geometry: 16 warps, split-N (each warp m16 x n32)
    const int lane  = tid & 31;
    const int wid   = tid >> 5;
    const int nhalf = wid >> 3;        // 0: ch 0-31, 1: ch 32-63
    const int wpg   = wid & 7;         // pillar group
    const int gid   = lane >> 2;
    const int tig   = lane & 3;
    const int gswz  = gid << 2;
    const int p0    = wpg * 16;
    const int cb    = nhalf * 32;

    float2 bias2[4];
    #pragma unroll
    for (int j = 0; j < 4; j++)
        bias2[j] = *(const float2*)(bbias + cb + j * 8 + 2 * tig);

    float2 s2[4], q2[4];
    #pragma unroll
    for (int j = 0; j < 4; j++) {
        s2[j] = make_float2(0.f, 0.f);
        q2[j] = make_float2(0.f, 0.f);
    }

    // staging geometry: e = tid + u*512 -> pillar e>>3, point e&7
    const int spb = tid >> 3;          // 0..63 (+64 via u)
    const int pt  = tid & 7;

    // hist geometry (threads 0..127 only)
    const int hswz = (tid & 7) << 2;
    float* hrow = At + tid * 192;

    int np2[2] = {0, 0};
    int primed = 0;

    for (int tile = blockIdx.x; tile < ntiles; tile += gridDim.x) {
        const int base = tile * TILE_P;

        if (!primed) {      // first tile only: load np + issue chunks 0-2 inline
            #pragma unroll
            for (int u = 0; u < 2; u++) {
                int gp = base + spb + u * 64;
                np2[u] = (gp < M) ? nump[gp] : 0;
            }
            #pragma unroll
            for (int c0 = 0; c0 < 3; c0++) {
                #pragma unroll
                for (int u = 0; u < 2; u++) {
                    int p = spb + u * 64;
                    if (np2[u] > c0 * 8) {
                        uint32_t dst = stg_b + c0 * (STG_BUF * 4) + (p * 9 + pt) * 16;
                        cp16(dst, feat + (size_t)(base + p) * 256 + c0 * 32 + pt * 4);
                    }
                }
                cp_commit();
            }
            primed = 1;
        }

        const int npt = (tid < TILE_P && base + tid < M) ? nump[base + tid] : 0;

        // zero At while loads fly (At free: previous GEMM consumed it before the
        // post-hist barrier of the previous iteration... guarded by barrier below)
        __syncthreads();
        {
            float4 z4 = make_float4(0.f, 0.f, 0.f, 0.f);
            float4* A4 = (float4*)At;
            #pragma unroll
            for (int i = tid; i < (TILE_P * KDIM) / 4; i += NTHREADS) A4[i] = z4;
        }

        // ---- pipelined histogram over 8 chunks ----
        #pragma unroll
        for (int ch = 0; ch < 8; ch++) {
            cp_wait(ch <= 5 ? 2 : 7 - ch);
            __syncthreads();
            if (ch < 5) {
                int cn = ch + 3;
                #pragma unroll
                for (int u = 0; u < 2; u++) {
                    int p = spb + u * 64;
                    if (np2[u] > cn * 8) {
                        uint32_t dst = stg_b + (cn & 3) * (STG_BUF * 4) + (p * 9 + pt) * 16;
                        cp16(dst, feat + (size_t)(base + p) * 256 + cn * 32 + pt * 4);
                    }
                }
                cp_commit();
            }
            if (tid < TILE_P) {
                const float* buf = stgf + (ch & 3) * STG_BUF;
                #pragma unroll
                for (int j = 0; j < 8; j++) {
                    if (ch * 8 + j < npt) {
                        float4 v = *(const float4*)(buf + (tid * 9 + j) * 4);
                        float z = v.z, r = v.w;
                        int bin = (int)((z - Z_MIN_F) * INV_BIN);
                        bin = max(0, min(NBINS - 1, bin));
                        int k3 = 3 * bin;
                        float* pc = hrow + ((k3)     ^ hswz);
                        float* pz = hrow + ((k3 + 1) ^ hswz);
                        float* pr = hrow + ((k3 + 2) ^ hswz);
                        float c0 = *pc;
                        float s0 = *pz;
                        float r0 = *pr;
                        *pc = c0 + 1.0f;
                        *pz = s0 + z;
                        *pr = r0 + r;
                    }
                }
            }
        }
        __syncthreads();   // all ring buffers consumed; At complete

        // ---- cross-tile prefetch: issue next tile's chunks 0-2 now ----
        {
            int nxt = tile + gridDim.x;
            if (nxt < ntiles) {
                int nb = nxt * TILE_P;
                #pragma unroll
                for (int u = 0; u < 2; u++) {
                    int gp = nb + spb + u * 64;
                    np2[u] = (gp < M) ? nump[gp] : 0;
                }
                #pragma unroll
                for (int c0 = 0; c0 < 3; c0++) {
                    #pragma unroll
                    for (int u = 0; u < 2; u++) {
                        int p = spb + u * 64;
                        if (np2[u] > c0 * 8) {
                            uint32_t dst = stg_b + c0 * (STG_BUF * 4) + (p * 9 + pt) * 16;
                            cp16(dst, feat + (size_t)(nb + p) * 256 + c0 * 32 + pt * 4);
                        }
                    }
                    cp_commit();
                }
            }
        }

        // ---- sums -> means, tf32-rounded ----
        #pragma unroll
        for (int idx = tid; idx < TILE_P * NBINS; idx += NTHREADS) {
            int bin = idx & 63;
            int p   = idx >> 6;
            int swz = (p & 7) << 2;
            float* row = At + p * 192;
            int k3 = 3 * bin;
            float* pc = row + ((k3)     ^ swz);
            float* pz = row + ((k3 + 1) ^ swz);
            float* pr = row + ((k3 + 2) ^ swz);
            float inv = __frcp_rn(*pc + EPS_MEAN);
            *pz = round_tf32(*pz * inv);
            *pr = round_tf32(*pr * inv);
        }
        __syncthreads();

        // ---- GEMM: warp = m16 (pillars p0..p0+15) x n32 (channels cb..cb+31) ----
        float d[4][4];
        #pragma unroll
        for (int j = 0; j < 4; j++) {
            d[j][0] = bias2[j].x; d[j][1] = bias2[j].y;
            d[j][2] = bias2[j].x; d[j][3] = bias2[j].y;
        }
        {
            const float* Ar0 = At + (p0 + gid) * 192;
            const float* Ar1 = Ar0 + 8 * 192;
            const float* Wg  = Wt + (cb + gid) * 192;
            #pragma unroll 4
            for (int s = 0; s < 24; s++) {
                int col  = ((s << 3) | tig) ^ gswz;
                int colx = col ^ 4;
                uint32_t a0 = __float_as_uint(Ar0[col]);
                uint32_t a1 = __float_as_uint(Ar1[col]);
                uint32_t a2 = __float_as_uint(Ar0[colx]);
                uint32_t a3 = __float_as_uint(Ar1[colx]);
                #pragma unroll
                for (int j = 0; j < 4; j++) {
                    const float* wr = Wg + j * (8 * 192);
                    uint32_t b0 = __float_as_uint(wr[col]);
                    uint32_t b1 = __float_as_uint(wr[colx]);
                    mma8(d[j], a0, a1, a2, a3, b0, b1);
                }
            }
        }

        // ---- epilogue: store x + BN register accumulation ----
        {
            int gp0 = base + p0 + gid;
            int gp1 = gp0 + 8;
            float2* gx = (float2*)g_X;
            int co = (cb >> 1);
            if (gp0 < M) {
                #pragma unroll
                for (int j = 0; j < 4; j++) {
                    gx[gp0 * 32 + co + j * 4 + tig] = make_float2(d[j][0], d[j][1]);
                    s2[j].x += d[j][0]; s2[j].y += d[j][1];
                    q2[j].x += d[j][0] * d[j][0];
                    q2[j].y += d[j][1] * d[j][1];
                }
            }
            if (gp1 < M) {
                #pragma unroll
                for (int j = 0; j < 4; j++) {
                    gx[gp1 * 32 + co + j * 4 + tig] = make_float2(d[j][2], d[j][3]);
                    s2[j].x += d[j][2]; s2[j].y += d[j][3];
                    q2[j].x += d[j][2] * d[j][2];
                    q2[j].y += d[j][3] * d[j][3];
                }
            }
        }
    }

    // ---- final BN reduction ----
    __syncthreads();
    float2* Ssm = (float2*)sm;       // At region dead
    float2* Qsm = Ssm + 2048;
    #pragma unroll
    for (int j = 0; j < 4; j++) {
        Ssm[tid * 4 + j] = s2[j];
        Qsm[tid * 4 + j] = q2[j];
    }
    __syncthreads();
    if (tid < FC) {
        int c  = tid;
        int nh = c >> 5;
        int jj = (c & 31) >> 3;
        int tg = (c >> 1) & 3;
        int e  = c & 1;
        float ts = 0.f, tq = 0.f;
        #pragma unroll
        for (int w = 0; w < 8; w++) {
            #pragma unroll
            for (int g = 0; g < 8; g++) {
                int src = ((nh * 8 + w) * 32 + g * 4 + tg) * 4 + jj;
                float2 vs = Ssm[src];
                float2 vq = Qsm[src];
                ts += e ? vs.y : vs.x;
                tq += e ? vq.y : vq.x;
            }
        }
        atomicAdd(&g_sum[c], ts);
        atomicAdd(&g_sqs[c], tq);
    }
}

// ---------------- kernel 2: finalize BN scale/shift ----------------
__global__ void finalize_kernel(const float* __restrict__ gamma,
                                const float* __restrict__ beta,
                                int M)
{
    int c = threadIdx.x;
    if (c < FC) {
        float invM = 1.0f / (float)M;
        float mu   = g_sum[c] * invM;
        float var  = g_sqs[c] * invM - mu * mu;
        var = fmaxf(var, 0.0f);
        float sc = gamma[c] * rsqrtf(var + EPS_BN);
        g_scale[c] = sc;
        g_shift[c] = beta[c] - mu * sc;
    }
}

// ---------------- kernel 3: normalize + ReLU + reset accumulators ----------------
__global__ void __launch_bounds__(256)
apply_kernel(float4* __restrict__ out, int M)
{
    int n4 = M * (FC / 4);
    int gid = blockIdx.x * blockDim.x + threadIdx.x;
    int stride = gridDim.x * blockDim.x;

    float4 x[4];
    int idx[4];
    #pragma unroll
    for (int u = 0; u < 4; u++) {
        int i = gid + u * stride;
        idx[u] = i;
        if (i < n4) x[u] = g_X[i];
    }
    #pragma unroll
    for (int u = 0; u < 4; u++) {
        int i = idx[u];
        if (i < n4) {
            int cbq = (i & 15) * 4;
            float4 sc = *(const float4*)&g_scale[cbq];
            float4 sh = *(const float4*)&g_shift[cbq];
            float4 r;
            r.x = fmaxf(fmaf(x[u].x, sc.x, sh.x), 0.0f);
            r.y = fmaxf(fmaf(x[u].y, sc.y, sh.y), 0.0f);
            r.z = fmaxf(fmaf(x[u].z, sc.z, sh.z), 0.0f);
            r.w = fmaxf(fmaf(x[u].w, sc.w, sh.w), 0.0f);
            out[i] = r;
        }
    }
    if (blockIdx.x == 0 && threadIdx.x < FC) {
        g_sum[threadIdx.x] = 0.0f;
        g_sqs[threadIdx.x] = 0.0f;
    }
}

// ---------------- launch ----------------
extern "C" void kernel_launch(void* const* d_in, const int* in_sizes, int n_in,
                              void* d_out, int out_size)
{
    const float* feat  = (const float*)d_in[0];
    const int*   nump  = (const int*)  d_in[1];
    const float* W     = (const float*)d_in[3];
    const float* bbias = (const float*)d_in[4];
    const float* gamma = (const float*)d_in[5];
    const float* beta  = (const float*)d_in[6];
    float4* out = (float4*)d_out;

    int M = in_sizes[1];
    if (M > MCAP) M = MCAP;
    int ntiles = (M + TILE_P - 1) / TILE_P;

    cudaFuncSetAttribute(main_kernel, cudaFuncAttributeMaxDynamicSharedMemorySize, SMEM_BYTES);

    int grid = ntiles < 148 ? ntiles : 148;
    main_kernel<<<grid, NTHREADS, SMEM_BYTES>>>(feat, nump, W, bbias, M, ntiles);
    finalize_kernel<<<1, 64>>>(gamma, beta, M);
    int n4 = M * (FC / 4);
    int blocks = ((n4 + 3) / 4 + 255) / 256;
    apply_kernel<<<blocks, 256>>>(out, M);
}